// round 15
// baseline (speedup 1.0000x reference)
#include <cuda_runtime.h>
#include <cuda_bf16.h>
#include <math.h>
#include <cstdint>

// Fixed shapes: z_i, z_j are [4096, 128] fp32
#define D       128
#define BHALF   4096
#define NROWS   8192
#define NT      64
#define NPAIRS  (NT * (NT + 1) / 2)   // 2080 triangular 128x128 tiles

// Scratch (__device__ globals; no allocation allowed)
__device__ __nv_bfloat16 g_zbf[NROWS * D];  // normalized rows, bf16 (2 MB, L2)
__device__ float g_S[NROWS];                // per-row sum of exp(sim), self excluded
__device__ float g_pos[NROWS];              // per-row positive logit
__device__ unsigned int g_ctr = 0;          // last-CTA ticket (reset each replay)

// ---------------------------------------------------------------------------
__device__ __forceinline__ uint32_t smem_u32(const void* p) {
    uint32_t a;
    asm("{ .reg .u64 t; cvta.to.shared.u64 t, %1; cvt.u32.u64 %0, t; }"
        : "=r"(a) : "l"(p));
    return a;
}
__device__ __forceinline__ void ldmatrix_x4(uint32_t* r, uint32_t a) {
    asm volatile("ldmatrix.sync.aligned.m8n8.x4.shared.b16 {%0,%1,%2,%3}, [%4];"
                 : "=r"(r[0]), "=r"(r[1]), "=r"(r[2]), "=r"(r[3]) : "r"(a));
}
__device__ __forceinline__ void mma_bf16(float* c, const uint32_t* a,
                                         const uint32_t* b) {
    asm volatile(
        "mma.sync.aligned.m16n8k16.row.col.f32.bf16.bf16.f32 "
        "{%0,%1,%2,%3}, {%4,%5,%6,%7}, {%8,%9}, {%0,%1,%2,%3};"
        : "+f"(c[0]), "+f"(c[1]), "+f"(c[2]), "+f"(c[3])
        : "r"(a[0]), "r"(a[1]), "r"(a[2]), "r"(a[3]), "r"(b[0]), "r"(b[1]));
}
#define CP_ASYNC16(dst, src) \
    asm volatile("cp.async.cg.shared.global [%0], [%1], 16;" \
                 :: "r"(dst), "l"(src) : "memory")
#define CP_COMMIT()  asm volatile("cp.async.commit_group;" ::: "memory")
#define CP_WAIT(n)   asm volatile("cp.async.wait_group %0;" :: "n"(n) : "memory")

// ---------------------------------------------------------------------------
// Kernel 1: row L2-normalize (1e-8 clamp) -> bf16, zero g_S.
// Two rows per warp (independent load chains -> MLP=2).
// ---------------------------------------------------------------------------
__global__ __launch_bounds__(256)
void k_normalize(const float* __restrict__ zi, const float* __restrict__ zj) {
    const int warp = threadIdx.x >> 5;
    const int lane = threadIdx.x & 31;
    const int row0 = blockIdx.x * 16 + warp * 2;   // this warp: row0, row0+1

    const float* s0 = (row0 < BHALF) ? (zi + (size_t)row0 * D)
                                     : (zj + (size_t)(row0 - BHALF) * D);
    const float* s1 = (row0 + 1 < BHALF) ? (zi + (size_t)(row0 + 1) * D)
                                         : (zj + (size_t)(row0 + 1 - BHALF) * D);
    float4 v0 = reinterpret_cast<const float4*>(s0)[lane];
    float4 v1 = reinterpret_cast<const float4*>(s1)[lane];
    float a0 = v0.x * v0.x + v0.y * v0.y + v0.z * v0.z + v0.w * v0.w;
    float a1 = v1.x * v1.x + v1.y * v1.y + v1.z * v1.z + v1.w * v1.w;
    #pragma unroll
    for (int o = 16; o > 0; o >>= 1) {
        a0 += __shfl_xor_sync(0xffffffffu, a0, o);
        a1 += __shfl_xor_sync(0xffffffffu, a1, o);
    }
    const float i0 = 1.0f / fmaxf(sqrtf(a0), 1e-8f);
    const float i1 = 1.0f / fmaxf(sqrtf(a1), 1e-8f);

    __nv_bfloat162* d0 = reinterpret_cast<__nv_bfloat162*>(g_zbf + (size_t)row0 * D);
    __nv_bfloat162* d1 = reinterpret_cast<__nv_bfloat162*>(g_zbf + (size_t)(row0 + 1) * D);
    d0[2 * lane + 0] = __floats2bfloat162_rn(v0.x * i0, v0.y * i0);
    d0[2 * lane + 1] = __floats2bfloat162_rn(v0.z * i0, v0.w * i0);
    d1[2 * lane + 0] = __floats2bfloat162_rn(v1.x * i1, v1.y * i1);
    d1[2 * lane + 1] = __floats2bfloat162_rn(v1.z * i1, v1.w * i1);
    if (lane == 0) { g_S[row0] = 0.0f; g_S[row0 + 1] = 0.0f; }
}

// ---------------------------------------------------------------------------
// Kernel 2: triangular (tj >= ti) 128x128 tiles via bf16 mma.sync (HMMA).
// 8 warps; warp (wr,wc) owns 64x32 = 4x4 m16n8 fragments.
// K=128 staged as TWO cp.async commit groups (64-wide halves) so MMA on
// half 0 overlaps the landing of half 1. XOR-swizzled rows -> conflict-free
// ldmatrix; B fragments fetched pairwise with ldmatrix.x4.
// Epilogue: exp(2*cos), diag mask, positive capture (row + mirror), row sums
// (quad shuffle + atomic), column sums (xor shuffle + atomic, off-diag only).
// Last CTA performs the final mean(log S - pos) reduction in-kernel.
// ---------------------------------------------------------------------------
__global__ __launch_bounds__(256, 2)
void k_sim(float* __restrict__ out) {
    extern __shared__ __align__(16) uint8_t smem[];
    uint8_t* sA = smem;              // 2 halves x (128 rows x 128 B)
    uint8_t* sB = smem + 32768;

    const int tid  = threadIdx.x;
    const int wid  = tid >> 5;
    const int lane = tid & 31;

    // Triangular decode
    int ti = 0, tj;
    {
        int rem = blockIdx.x, rowlen = NT;
        while (rem >= rowlen) { rem -= rowlen; rowlen--; ti++; }
        tj = ti + rem;
    }
    const int I0 = ti * 128, J0 = tj * 128;
    const bool diag = (ti == tj);

    const int wr = wid >> 2;          // 0..1 : 64-row block
    const int wc = wid & 3;           // 0..3 : 32-col block
    const uint32_t sa = smem_u32(sA), sb = smem_u32(sB);

    // ldmatrix lane assignments (all swizzles reduce to lane&7)
    const int a_row = wr * 64 + ((lane >> 3) & 1) * 8 + (lane & 7);
    const int a_cb  = lane >> 4;                     // k-octet 0/1 within k16
    const int b_row4 = wc * 32 + ((lane >> 4) << 3) + (lane & 7); // +ni*8 later
    const int b_cb   = (lane >> 3) & 1;
    const int swz    = lane & 7;

    // ---- Stage K halves as two commit groups (512 chunks A + 512 B each) ----
    #pragma unroll
    for (int h = 0; h < 2; h++) {
        #pragma unroll
        for (int i = 0; i < 4; i++) {
            const int e = tid + 256 * i;         // 0..1023
            const int r = e >> 3, c = e & 7;     // row, 16B chunk within half
            const uint32_t off = (uint32_t)h * 16384u + (uint32_t)r * 128u
                               + (uint32_t)((c ^ (r & 7)) << 4);
            const size_t gofs = (size_t)r * D + h * 64 + c * 8;
            CP_ASYNC16(sa + off, (const void*)(g_zbf + (size_t)I0 * D + gofs));
            CP_ASYNC16(sb + off, (const void*)(g_zbf + (size_t)J0 * D + gofs));
        }
        CP_COMMIT();
    }

    float acc[4][4][4];
    #pragma unroll
    for (int mi = 0; mi < 4; mi++)
        #pragma unroll
        for (int ni = 0; ni < 4; ni++)
            #pragma unroll
            for (int f = 0; f < 4; f++) acc[mi][ni][f] = 0.0f;

    // ---- Main loop: two halves x 4 chunks of k16 ----
    #pragma unroll
    for (int h = 0; h < 2; h++) {
        if (h == 0) CP_WAIT(1); else CP_WAIT(0);
        __syncthreads();
        const uint32_t hbase = (uint32_t)h * 16384u;
        #pragma unroll
        for (int kc = 0; kc < 4; kc++) {
            uint32_t af[4][4], bf[2][4];
            #pragma unroll
            for (int mi = 0; mi < 4; mi++) {
                const uint32_t addr = sa + hbase
                    + (uint32_t)(a_row + mi * 16) * 128u
                    + (uint32_t)(((kc * 2 + a_cb) ^ swz) << 4);
                ldmatrix_x4(af[mi], addr);
            }
            #pragma unroll
            for (int np = 0; np < 2; np++) {     // ni pair {0,1}, {2,3}
                const uint32_t addr = sb + hbase
                    + (uint32_t)(b_row4 + np * 16) * 128u
                    + (uint32_t)(((kc * 2 + b_cb) ^ swz) << 4);
                ldmatrix_x4(bf[np], addr);       // r0,r1 = ni ; r2,r3 = ni+1
            }
            #pragma unroll
            for (int mi = 0; mi < 4; mi++)
                #pragma unroll
                for (int ni = 0; ni < 4; ni++)
                    mma_bf16(acc[mi][ni], af[mi], bf[ni >> 1] + (ni & 1) * 2);
        }
        if (h == 0) __syncthreads();   // half-0 reads done before nothing else; keep order
    }

    // ---- Epilogue ----
    const int trow  = lane >> 2;
    const int tcol2 = (lane & 3) * 2;

    float cs[4][2];
    #pragma unroll
    for (int ni = 0; ni < 4; ni++) { cs[ni][0] = 0.0f; cs[ni][1] = 0.0f; }

    #pragma unroll
    for (int mi = 0; mi < 4; mi++) {
        const int gi0 = I0 + wr * 64 + mi * 16 + trow;
        const int gi1 = gi0 + 8;
        const int p0 = gi0 ^ BHALF, p1 = gi1 ^ BHALF;
        float rs0 = 0.0f, rs1 = 0.0f;
        #pragma unroll
        for (int ni = 0; ni < 4; ni++) {
            const int gj = J0 + wc * 32 + ni * 8 + tcol2;
            const float* c = acc[mi][ni];
            float s0 = c[0] + c[0], s1 = c[1] + c[1];   // sim = cos / 0.5
            float s2 = c[2] + c[2], s3 = c[3] + c[3];
            float e0 = __expf(s0), e1 = __expf(s1);
            float e2 = __expf(s2), e3 = __expf(s3);
            if (diag) {                                  // mask self-similarity
                if (gj     == gi0) e0 = 0.0f;
                if (gj + 1 == gi0) e1 = 0.0f;
                if (gj     == gi1) e2 = 0.0f;
                if (gj + 1 == gi1) e3 = 0.0f;
            }
            if (gj     == p0) { g_pos[gi0] = s0; g_pos[gj]     = s0; }
            if (gj + 1 == p0) { g_pos[gi0] = s1; g_pos[gj + 1] = s1; }
            if (gj     == p1) { g_pos[gi1] = s2; g_pos[gj]     = s2; }
            if (gj + 1 == p1) { g_pos[gi1] = s3; g_pos[gj + 1] = s3; }
            rs0 += e0 + e1;
            rs1 += e2 + e3;
            cs[ni][0] += e0 + e2;     // transpose (column) contribution
            cs[ni][1] += e1 + e3;
        }
        rs0 += __shfl_xor_sync(0xffffffffu, rs0, 1);
        rs0 += __shfl_xor_sync(0xffffffffu, rs0, 2);
        rs1 += __shfl_xor_sync(0xffffffffu, rs1, 1);
        rs1 += __shfl_xor_sync(0xffffffffu, rs1, 2);
        if ((lane & 3) == 0) {
            atomicAdd(&g_S[gi0], rs0);
            atomicAdd(&g_S[gi1], rs1);
        }
    }

    if (!diag) {
        #pragma unroll
        for (int ni = 0; ni < 4; ni++) {
            float c0 = cs[ni][0], c1 = cs[ni][1];
            #pragma unroll
            for (int o = 4; o < 32; o <<= 1) {
                c0 += __shfl_xor_sync(0xffffffffu, c0, o);
                c1 += __shfl_xor_sync(0xffffffffu, c1, o);
            }
            if (lane < 4) {
                const int gj = J0 + wc * 32 + ni * 8 + lane * 2;
                atomicAdd(&g_S[gj],     c0);
                atomicAdd(&g_S[gj + 1], c1);
            }
        }
    }

    // ---- Last-CTA final reduction: loss = mean(log S - pos) ----
    __shared__ bool s_last;
    __syncthreads();
    if (tid == 0) {
        __threadfence();
        s_last = (atomicAdd(&g_ctr, 1u) == (unsigned)(NPAIRS - 1));
    }
    __syncthreads();
    if (s_last) {
        float acc2 = 0.0f;
        for (int i = tid; i < NROWS; i += 256)
            acc2 += logf(__ldcg(&g_S[i])) - __ldcg(&g_pos[i]);
        #pragma unroll
        for (int o = 16; o > 0; o >>= 1)
            acc2 += __shfl_down_sync(0xffffffffu, acc2, o);
        __shared__ float ws[8];
        if ((tid & 31) == 0) ws[tid >> 5] = acc2;
        __syncthreads();
        if (tid == 0) {
            float tot = 0.0f;
            #pragma unroll
            for (int w = 0; w < 8; w++) tot += ws[w];
            out[0] = tot * (1.0f / (float)NROWS);
            g_ctr = 0;                 // reset for next graph replay
        }
    }
}

// ---------------------------------------------------------------------------
extern "C" void kernel_launch(void* const* d_in, const int* in_sizes, int n_in,
                              void* d_out, int out_size) {
    (void)in_sizes; (void)n_in; (void)out_size;
    const float* zi = (const float*)d_in[0];
    const float* zj = (const float*)d_in[1];
    float* out = (float*)d_out;

    cudaFuncSetAttribute(k_sim, cudaFuncAttributeMaxDynamicSharedMemorySize, 65536);

    k_normalize<<<NROWS / 16, 256>>>(zi, zj);
    k_sim<<<NPAIRS, 256, 65536>>>(out);
}